// round 10
// baseline (speedup 1.0000x reference)
#include <cuda_runtime.h>
#include <cuda_bf16.h>
#include <cstdint>

// Shapes fixed: B=4, N=2048, C=1024, H=16, d=64
#define NEGV -10000000.0f

__device__ float g_qkv[25165824];  // [8192, 3072]
__device__ float g_att[8388608];   // [8192, 1024]

// Fast exp on the FMA pipe (MUFU.EX2 rt=8 would be a throughput wall).
__device__ __forceinline__ float fexp(float x) {
    float y = x * 1.4426950408889634f;
    float fl = floorf(y);
    float f = y - fl;
    float p = 1.5252733e-4f;
    p = p * f + 1.3333558e-3f;
    p = p * f + 9.6181291e-3f;
    p = p * f + 5.5504109e-2f;
    p = p * f + 2.4022651e-1f;
    p = p * f + 6.9314718e-1f;
    p = p * f + 1.0f;
    int e = (int)fl;
    e = e < -126 ? -126 : e;
    return p * __int_as_float((e + 127) << 23);
}

__device__ __forceinline__ uint32_t f2tf32(float f) {
    uint32_t r;
    asm("cvt.rna.tf32.f32 %0, %1;" : "=r"(r) : "f"(f));
    return r;
}

// D += A(16x8) @ B(8x8), tf32 inputs, fp32 accum
__device__ __forceinline__ void mma8(float* c, const uint32_t* a, const uint32_t* b) {
    asm volatile(
        "mma.sync.aligned.m16n8k8.row.col.f32.tf32.tf32.f32 "
        "{%0,%1,%2,%3}, {%4,%5,%6,%7}, {%8,%9}, {%0,%1,%2,%3};"
        : "+f"(c[0]), "+f"(c[1]), "+f"(c[2]), "+f"(c[3])
        : "r"(a[0]), "r"(a[1]), "r"(a[2]), "r"(a[3]), "r"(b[0]), "r"(b[1]));
}

// ---------------------------------------------------------------------------
// 128x128x8 GEMM, tf32x3 split (hi*hi + hi*lo + lo*hi) -> ~fp32 accuracy.
// 8 warps (2x4), warp tile 64x32, mma m16n8k8. C = A[M,K]@B[K,N] (+bias).
// ---------------------------------------------------------------------------
__global__ __launch_bounds__(256) void gemm_tf32x3(
    const float* __restrict__ A, const float* __restrict__ B,
    const float* __restrict__ bias, float* __restrict__ C,
    int M, int N, int K)
{
    __shared__ float Ah[8][136], Al[8][136], Bh[8][136], Bl[8][136];

    const int tid  = threadIdx.x;
    const int brow = blockIdx.y * 128;
    const int bcol = blockIdx.x * 128;
    const int warp = tid >> 5, lane = tid & 31;
    const int g = lane >> 2, t = lane & 3;
    const int wm = (warp & 1) * 64;
    const int wn = (warp >> 1) * 32;

    const int a_row = tid >> 1, a_k = (tid & 1) * 4;
    const int b_k   = tid >> 5, b_c = (tid & 31) * 4;
    const float* Ap = A + (size_t)(brow + a_row) * K + a_k;
    const float* Bp = B + (size_t)b_k * N + bcol + b_c;

    float acc[4][4][4];
    #pragma unroll
    for (int mt = 0; mt < 4; mt++)
        #pragma unroll
        for (int nt = 0; nt < 4; nt++)
            #pragma unroll
            for (int e = 0; e < 4; e++) acc[mt][nt][e] = 0.f;

    for (int kt = 0; kt < K; kt += 8) {
        float4 av = *(const float4*)(Ap + kt);
        float4 bv = *(const float4*)(Bp + (size_t)kt * N);
        float va[4] = {av.x, av.y, av.z, av.w};
        float vb[4] = {bv.x, bv.y, bv.z, bv.w};
        #pragma unroll
        for (int i = 0; i < 4; i++) {
            float hi = __uint_as_float(f2tf32(va[i]));
            Ah[a_k + i][a_row] = hi;
            Al[a_k + i][a_row] = __uint_as_float(f2tf32(va[i] - hi));
        }
        #pragma unroll
        for (int i = 0; i < 4; i++) {
            float hi = __uint_as_float(f2tf32(vb[i]));
            Bh[b_k][b_c + i] = hi;
            Bl[b_k][b_c + i] = __uint_as_float(f2tf32(vb[i] - hi));
        }
        __syncthreads();

        uint32_t ah[4][4], al[4][4], bh[4][2], bl[4][2];
        #pragma unroll
        for (int mt = 0; mt < 4; mt++) {
            int r0 = wm + mt * 16 + g;
            ah[mt][0] = __float_as_uint(Ah[t][r0]);
            ah[mt][1] = __float_as_uint(Ah[t][r0 + 8]);
            ah[mt][2] = __float_as_uint(Ah[t + 4][r0]);
            ah[mt][3] = __float_as_uint(Ah[t + 4][r0 + 8]);
            al[mt][0] = __float_as_uint(Al[t][r0]);
            al[mt][1] = __float_as_uint(Al[t][r0 + 8]);
            al[mt][2] = __float_as_uint(Al[t + 4][r0]);
            al[mt][3] = __float_as_uint(Al[t + 4][r0 + 8]);
        }
        #pragma unroll
        for (int nt = 0; nt < 4; nt++) {
            int c0 = wn + nt * 8 + g;
            bh[nt][0] = __float_as_uint(Bh[t][c0]);
            bh[nt][1] = __float_as_uint(Bh[t + 4][c0]);
            bl[nt][0] = __float_as_uint(Bl[t][c0]);
            bl[nt][1] = __float_as_uint(Bl[t + 4][c0]);
        }
        #pragma unroll
        for (int mt = 0; mt < 4; mt++)
            #pragma unroll
            for (int nt = 0; nt < 4; nt++) {
                mma8(acc[mt][nt], al[mt], bh[nt]);
                mma8(acc[mt][nt], ah[mt], bl[nt]);
                mma8(acc[mt][nt], ah[mt], bh[nt]);
            }
        __syncthreads();
    }

    #pragma unroll
    for (int mt = 0; mt < 4; mt++)
        #pragma unroll
        for (int nt = 0; nt < 4; nt++) {
            int row0 = brow + wm + mt * 16 + g;
            int col  = bcol + wn + nt * 8 + t * 2;
            float bx = 0.f, by = 0.f;
            if (bias) { bx = bias[col]; by = bias[col + 1]; }
            float2 v0 = make_float2(acc[mt][nt][0] + bx, acc[mt][nt][1] + by);
            float2 v1 = make_float2(acc[mt][nt][2] + bx, acc[mt][nt][3] + by);
            *(float2*)&C[(size_t)row0 * N + col]       = v0;
            *(float2*)&C[(size_t)(row0 + 8) * N + col] = v1;
        }
}

// ---------------------------------------------------------------------------
// Flash attention with tf32 mma. CTA = (b, h, 64 q-rows), 128 threads (4 warps,
// each owns 16 q-rows). k-blocks of 64, online softmax on mma fragments.
// ---------------------------------------------------------------------------
constexpr int FQ = 72;                           // bank-friendly stride
constexpr int FLASH_SMEM = 4 * 64 * FQ * 4;      // Qs,Ks,Vs,Ps = 73728 B

__global__ __launch_bounds__(128) void flash_mma(
    const float* __restrict__ qkv, const int* __restrict__ am,
    const int* __restrict__ pm, float* __restrict__ out)
{
    extern __shared__ float sm[];
    float* Qs = sm;             // [q=64][d=64] tf32, pre-scaled
    float* Ks = Qs + 64 * FQ;   // [k=64][d=64] tf32
    float* Vs = Ks + 64 * FQ;   // [k=64][d=64] tf32
    float* Ps = Vs + 64 * FQ;   // [q=64][k=64] tf32

    const int qb  = blockIdx.x * 64;
    const int h   = blockIdx.y;
    const int b   = blockIdx.z;
    const int tid = threadIdx.x;
    const int warp = tid >> 5, lane = tid & 31;
    const int g = lane >> 2, t = lane & 3;
    const int wq = warp * 16;

    const size_t base = (size_t)b * 2048 * 3072 + h * 64;

    // Load Q tile (tf32, pre-scaled by d^-0.5 = 0.125)
    for (int i = tid; i < 1024; i += 128) {
        int r = i >> 4, c = (i & 15) << 2;
        float4 v = *(const float4*)(qkv + base + (size_t)(qb + r) * 3072 + c);
        float4 q;
        q.x = __uint_as_float(f2tf32(v.x * 0.125f));
        q.y = __uint_as_float(f2tf32(v.y * 0.125f));
        q.z = __uint_as_float(f2tf32(v.z * 0.125f));
        q.w = __uint_as_float(f2tf32(v.w * 0.125f));
        *(float4*)&Qs[r * FQ + c] = q;
    }

    float m0 = -1.0e30f, m1 = -1.0e30f, l0 = 0.f, l1 = 0.f;
    float o[8][4];
    #pragma unroll
    for (int nt = 0; nt < 8; nt++)
        #pragma unroll
        for (int e = 0; e < 4; e++) o[nt][e] = 0.f;

    for (int kb = 0; kb < 2048; kb += 64) {
        __syncthreads();
        // Load K, V tiles (tf32)
        for (int i = tid; i < 1024; i += 128) {
            int r = i >> 4, c = (i & 15) << 2;
            const float* src = qkv + base + (size_t)(kb + r) * 3072;
            float4 kv = *(const float4*)(src + 1024 + c);
            float4 vv = *(const float4*)(src + 2048 + c);
            float4 ko, vo;
            ko.x = __uint_as_float(f2tf32(kv.x));
            ko.y = __uint_as_float(f2tf32(kv.y));
            ko.z = __uint_as_float(f2tf32(kv.z));
            ko.w = __uint_as_float(f2tf32(kv.w));
            vo.x = __uint_as_float(f2tf32(vv.x));
            vo.y = __uint_as_float(f2tf32(vv.y));
            vo.z = __uint_as_float(f2tf32(vv.z));
            vo.w = __uint_as_float(f2tf32(vv.w));
            *(float4*)&Ks[r * FQ + c] = ko;
            *(float4*)&Vs[r * FQ + c] = vo;
        }
        __syncthreads();

        // S = Q @ K^T : m16 (q) x n8 (k-cols) x k8 (d)
        float s[8][4];
        #pragma unroll
        for (int nt = 0; nt < 8; nt++)
            #pragma unroll
            for (int e = 0; e < 4; e++) s[nt][e] = 0.f;

        #pragma unroll
        for (int ks = 0; ks < 8; ks++) {
            uint32_t a[4];
            int rb = (wq + g) * FQ + ks * 8;
            a[0] = __float_as_uint(Qs[rb + t]);
            a[1] = __float_as_uint(Qs[rb + 8 * FQ + t]);
            a[2] = __float_as_uint(Qs[rb + t + 4]);
            a[3] = __float_as_uint(Qs[rb + 8 * FQ + t + 4]);
            #pragma unroll
            for (int nt = 0; nt < 8; nt++) {
                uint32_t bb[2];
                int cb = (nt * 8 + g) * FQ + ks * 8;
                bb[0] = __float_as_uint(Ks[cb + t]);
                bb[1] = __float_as_uint(Ks[cb + t + 4]);
                mma8(s[nt], a, bb);
            }
        }

        // Masks: row0 = qb+wq+g, row1 = +8; cols = kb + nt*8 + t*2 + {0,1}
        {
            int qr0 = qb + wq + g;
            #pragma unroll
            for (int nt = 0; nt < 8; nt++) {
                int col = kb + nt * 8 + t * 2;
                int2 pv = *(const int2*)(pm + b * 2048 + col);
                int2 a0 = *(const int2*)(am + (size_t)qr0 * 2048 + col);
                int2 a1 = *(const int2*)(am + (size_t)(qr0 + 8) * 2048 + col);
                if (a0.x <= 0 || pv.x > 0) s[nt][0] = NEGV;
                if (a0.y <= 0 || pv.y > 0) s[nt][1] = NEGV;
                if (a1.x <= 0 || pv.x > 0) s[nt][2] = NEGV;
                if (a1.y <= 0 || pv.y > 0) s[nt][3] = NEGV;
            }
        }

        // Online softmax. Row is spread over the 4 lanes of a quad -> shfl 1,2.
        float mx0 = -1.0e30f, mx1 = -1.0e30f;
        #pragma unroll
        for (int nt = 0; nt < 8; nt++) {
            mx0 = fmaxf(mx0, fmaxf(s[nt][0], s[nt][1]));
            mx1 = fmaxf(mx1, fmaxf(s[nt][2], s[nt][3]));
        }
        #pragma unroll
        for (int off = 1; off <= 2; off <<= 1) {
            mx0 = fmaxf(mx0, __shfl_xor_sync(0xffffffffu, mx0, off));
            mx1 = fmaxf(mx1, __shfl_xor_sync(0xffffffffu, mx1, off));
        }
        float mn0 = fmaxf(m0, mx0), mn1 = fmaxf(m1, mx1);
        float al0 = fexp(m0 - mn0), al1 = fexp(m1 - mn1);
        m0 = mn0; m1 = mn1;

        float sum0 = 0.f, sum1 = 0.f;
        #pragma unroll
        for (int nt = 0; nt < 8; nt++) {
            s[nt][0] = fexp(s[nt][0] - mn0);
            s[nt][1] = fexp(s[nt][1] - mn0);
            s[nt][2] = fexp(s[nt][2] - mn1);
            s[nt][3] = fexp(s[nt][3] - mn1);
            sum0 += s[nt][0] + s[nt][1];
            sum1 += s[nt][2] + s[nt][3];
        }
        #pragma unroll
        for (int off = 1; off <= 2; off <<= 1) {
            sum0 += __shfl_xor_sync(0xffffffffu, sum0, off);
            sum1 += __shfl_xor_sync(0xffffffffu, sum1, off);
        }
        l0 = l0 * al0 + sum0;
        l1 = l1 * al1 + sum1;
        #pragma unroll
        for (int nt = 0; nt < 8; nt++) {
            o[nt][0] *= al0; o[nt][1] *= al0;
            o[nt][2] *= al1; o[nt][3] *= al1;
        }

        // P -> smem (tf32), rows wq+g and wq+8+g, cols nt*8 + t*2
        #pragma unroll
        for (int nt = 0; nt < 8; nt++) {
            float2 p0 = make_float2(__uint_as_float(f2tf32(s[nt][0])),
                                    __uint_as_float(f2tf32(s[nt][1])));
            float2 p1 = make_float2(__uint_as_float(f2tf32(s[nt][2])),
                                    __uint_as_float(f2tf32(s[nt][3])));
            *(float2*)&Ps[(wq + g) * FQ + nt * 8 + t * 2]     = p0;
            *(float2*)&Ps[(wq + 8 + g) * FQ + nt * 8 + t * 2] = p1;
        }
        __syncwarp();

        // O += P @ V : m16 (q) x n8 (d-cols) x k8 (k)
        #pragma unroll
        for (int ks = 0; ks < 8; ks++) {
            uint32_t a[4];
            int rb = (wq + g) * FQ + ks * 8;
            a[0] = __float_as_uint(Ps[rb + t]);
            a[1] = __float_as_uint(Ps[rb + 8 * FQ + t]);
            a[2] = __float_as_uint(Ps[rb + t + 4]);
            a[3] = __float_as_uint(Ps[rb + 8 * FQ + t + 4]);
            #pragma unroll
            for (int nt = 0; nt < 8; nt++) {
                uint32_t bb[2];
                int vb0 = (ks * 8 + t) * FQ + nt * 8 + g;
                bb[0] = __float_as_uint(Vs[vb0]);
                bb[1] = __float_as_uint(Vs[vb0 + 4 * FQ]);
                mma8(o[nt], a, bb);
            }
        }
        __syncwarp();
    }

    // Epilogue: normalize, write [B*N, C], col = h*64 + d
    float inv0 = 1.0f / l0, inv1 = 1.0f / l1;
    int row0 = b * 2048 + qb + wq + g;
    #pragma unroll
    for (int nt = 0; nt < 8; nt++) {
        int col = h * 64 + nt * 8 + t * 2;
        float2 v0 = make_float2(o[nt][0] * inv0, o[nt][1] * inv0);
        float2 v1 = make_float2(o[nt][2] * inv1, o[nt][3] * inv1);
        *(float2*)&out[(size_t)row0 * 1024 + col]       = v0;
        *(float2*)&out[(size_t)(row0 + 8) * 1024 + col] = v1;
    }
}

// ---------------------------------------------------------------------------
extern "C" void kernel_launch(void* const* d_in, const int* in_sizes, int n_in,
                              void* d_out, int out_size) {
    const float* inputs = (const float*)d_in[0];
    const int*   amask  = (const int*)d_in[1];
    const int*   pmask  = (const int*)d_in[2];
    const float* Wqkv   = (const float*)d_in[3];
    const float* Wproj  = (const float*)d_in[4];
    const float* bproj  = (const float*)d_in[5];
    float* out = (float*)d_out;

    float *qkv_p, *att_p;
    cudaGetSymbolAddress((void**)&qkv_p, g_qkv);
    cudaGetSymbolAddress((void**)&att_p, g_att);

    // 1) QKV = X @ W_qkv : [8192,1024] x [1024,3072]  (tf32x3)
    gemm_tf32x3<<<dim3(24, 64), 256>>>(inputs, Wqkv, nullptr, qkv_p,
                                       8192, 3072, 1024);

    // 2) Flash attention (tf32 mma)
    cudaFuncSetAttribute(flash_mma, cudaFuncAttributeMaxDynamicSharedMemorySize,
                         FLASH_SMEM);
    flash_mma<<<dim3(32, 16, 4), 128, FLASH_SMEM>>>(qkv_p, amask, pmask, att_p);

    // 3) Out = Att @ W_proj + b : [8192,1024] x [1024,1024]  (tf32x3)
    gemm_tf32x3<<<dim3(8, 64), 256>>>(att_p, Wproj, bproj, out,
                                      8192, 1024, 1024);
}

// round 11
// speedup vs baseline: 1.0043x; 1.0043x over previous
#include <cuda_runtime.h>
#include <cuda_bf16.h>
#include <cstdint>

// Shapes fixed: B=4, N=2048, C=1024, H=16, d=64
#define NEGV -10000000.0f

__device__ float g_qkv[25165824];  // [8192, 3072]
__device__ float g_att[8388608];   // [8192, 1024]

// Fast exp on the FMA pipe (MUFU.EX2 rt=8 would be a throughput wall).
__device__ __forceinline__ float fexp(float x) {
    float y = x * 1.4426950408889634f;
    float fl = floorf(y);
    float f = y - fl;
    float p = 1.5252733e-4f;
    p = p * f + 1.3333558e-3f;
    p = p * f + 9.6181291e-3f;
    p = p * f + 5.5504109e-2f;
    p = p * f + 2.4022651e-1f;
    p = p * f + 6.9314718e-1f;
    p = p * f + 1.0f;
    int e = (int)fl;
    e = e < -126 ? -126 : e;
    return p * __int_as_float((e + 127) << 23);
}

__device__ __forceinline__ uint32_t f2tf32(float f) {
    uint32_t r;
    asm("cvt.rna.tf32.f32 %0, %1;" : "=r"(r) : "f"(f));
    return r;
}

// D += A(16x8) @ B(8x8), tf32 inputs, fp32 accum
__device__ __forceinline__ void mma8(float* c, const uint32_t* a, const uint32_t* b) {
    asm volatile(
        "mma.sync.aligned.m16n8k8.row.col.f32.tf32.tf32.f32 "
        "{%0,%1,%2,%3}, {%4,%5,%6,%7}, {%8,%9}, {%0,%1,%2,%3};"
        : "+f"(c[0]), "+f"(c[1]), "+f"(c[2]), "+f"(c[3])
        : "r"(a[0]), "r"(a[1]), "r"(a[2]), "r"(a[3]), "r"(b[0]), "r"(b[1]));
}

// ---------------------------------------------------------------------------
// 128x128x8 GEMM, tf32x3 split (hi*hi + hi*lo + lo*hi) -> ~fp32 accuracy.
// 8 warps (2x4), warp tile 64x32, mma m16n8k8. C = A[M,K]@B[K,N] (+bias).
// ---------------------------------------------------------------------------
__global__ __launch_bounds__(256) void gemm_tf32x3(
    const float* __restrict__ A, const float* __restrict__ B,
    const float* __restrict__ bias, float* __restrict__ C,
    int M, int N, int K)
{
    __shared__ float Ah[8][136], Al[8][136], Bh[8][136], Bl[8][136];

    const int tid  = threadIdx.x;
    const int brow = blockIdx.y * 128;
    const int bcol = blockIdx.x * 128;
    const int warp = tid >> 5, lane = tid & 31;
    const int g = lane >> 2, t = lane & 3;
    const int wm = (warp & 1) * 64;
    const int wn = (warp >> 1) * 32;

    const int a_row = tid >> 1, a_k = (tid & 1) * 4;
    const int b_k   = tid >> 5, b_c = (tid & 31) * 4;
    const float* Ap = A + (size_t)(brow + a_row) * K + a_k;
    const float* Bp = B + (size_t)b_k * N + bcol + b_c;

    float acc[4][4][4];
    #pragma unroll
    for (int mt = 0; mt < 4; mt++)
        #pragma unroll
        for (int nt = 0; nt < 4; nt++)
            #pragma unroll
            for (int e = 0; e < 4; e++) acc[mt][nt][e] = 0.f;

    for (int kt = 0; kt < K; kt += 8) {
        float4 av = *(const float4*)(Ap + kt);
        float4 bv = *(const float4*)(Bp + (size_t)kt * N);
        float va[4] = {av.x, av.y, av.z, av.w};
        float vb[4] = {bv.x, bv.y, bv.z, bv.w};
        #pragma unroll
        for (int i = 0; i < 4; i++) {
            float hi = __uint_as_float(f2tf32(va[i]));
            Ah[a_k + i][a_row] = hi;
            Al[a_k + i][a_row] = __uint_as_float(f2tf32(va[i] - hi));
        }
        #pragma unroll
        for (int i = 0; i < 4; i++) {
            float hi = __uint_as_float(f2tf32(vb[i]));
            Bh[b_k][b_c + i] = hi;
            Bl[b_k][b_c + i] = __uint_as_float(f2tf32(vb[i] - hi));
        }
        __syncthreads();

        uint32_t ah[4][4], al[4][4], bh[4][2], bl[4][2];
        #pragma unroll
        for (int mt = 0; mt < 4; mt++) {
            int r0 = wm + mt * 16 + g;
            ah[mt][0] = __float_as_uint(Ah[t][r0]);
            ah[mt][1] = __float_as_uint(Ah[t][r0 + 8]);
            ah[mt][2] = __float_as_uint(Ah[t + 4][r0]);
            ah[mt][3] = __float_as_uint(Ah[t + 4][r0 + 8]);
            al[mt][0] = __float_as_uint(Al[t][r0]);
            al[mt][1] = __float_as_uint(Al[t][r0 + 8]);
            al[mt][2] = __float_as_uint(Al[t + 4][r0]);
            al[mt][3] = __float_as_uint(Al[t + 4][r0 + 8]);
        }
        #pragma unroll
        for (int nt = 0; nt < 4; nt++) {
            int c0 = wn + nt * 8 + g;
            bh[nt][0] = __float_as_uint(Bh[t][c0]);
            bh[nt][1] = __float_as_uint(Bh[t + 4][c0]);
            bl[nt][0] = __float_as_uint(Bl[t][c0]);
            bl[nt][1] = __float_as_uint(Bl[t + 4][c0]);
        }
        #pragma unroll
        for (int mt = 0; mt < 4; mt++)
            #pragma unroll
            for (int nt = 0; nt < 4; nt++) {
                mma8(acc[mt][nt], al[mt], bh[nt]);
                mma8(acc[mt][nt], ah[mt], bl[nt]);
                mma8(acc[mt][nt], ah[mt], bh[nt]);
            }
        __syncthreads();
    }

    #pragma unroll
    for (int mt = 0; mt < 4; mt++)
        #pragma unroll
        for (int nt = 0; nt < 4; nt++) {
            int row0 = brow + wm + mt * 16 + g;
            int col  = bcol + wn + nt * 8 + t * 2;
            float bx = 0.f, by = 0.f;
            if (bias) { bx = bias[col]; by = bias[col + 1]; }
            float2 v0 = make_float2(acc[mt][nt][0] + bx, acc[mt][nt][1] + by);
            float2 v1 = make_float2(acc[mt][nt][2] + bx, acc[mt][nt][3] + by);
            *(float2*)&C[(size_t)row0 * N + col]       = v0;
            *(float2*)&C[(size_t)(row0 + 8) * N + col] = v1;
        }
}

// ---------------------------------------------------------------------------
// Flash attention with tf32 mma. CTA = (b, h, 64 q-rows), 128 threads (4 warps,
// each owns 16 q-rows). k-blocks of 64, online softmax on mma fragments.
// ---------------------------------------------------------------------------
constexpr int FQ = 72;                           // bank-friendly stride
constexpr int FLASH_SMEM = 4 * 64 * FQ * 4;      // Qs,Ks,Vs,Ps = 73728 B

__global__ __launch_bounds__(128) void flash_mma(
    const float* __restrict__ qkv, const int* __restrict__ am,
    const int* __restrict__ pm, float* __restrict__ out)
{
    extern __shared__ float sm[];
    float* Qs = sm;             // [q=64][d=64] tf32, pre-scaled
    float* Ks = Qs + 64 * FQ;   // [k=64][d=64] tf32
    float* Vs = Ks + 64 * FQ;   // [k=64][d=64] tf32
    float* Ps = Vs + 64 * FQ;   // [q=64][k=64] tf32

    const int qb  = blockIdx.x * 64;
    const int h   = blockIdx.y;
    const int b   = blockIdx.z;
    const int tid = threadIdx.x;
    const int warp = tid >> 5, lane = tid & 31;
    const int g = lane >> 2, t = lane & 3;
    const int wq = warp * 16;

    const size_t base = (size_t)b * 2048 * 3072 + h * 64;

    // Load Q tile (tf32, pre-scaled by d^-0.5 = 0.125)
    for (int i = tid; i < 1024; i += 128) {
        int r = i >> 4, c = (i & 15) << 2;
        float4 v = *(const float4*)(qkv + base + (size_t)(qb + r) * 3072 + c);
        float4 q;
        q.x = __uint_as_float(f2tf32(v.x * 0.125f));
        q.y = __uint_as_float(f2tf32(v.y * 0.125f));
        q.z = __uint_as_float(f2tf32(v.z * 0.125f));
        q.w = __uint_as_float(f2tf32(v.w * 0.125f));
        *(float4*)&Qs[r * FQ + c] = q;
    }

    float m0 = -1.0e30f, m1 = -1.0e30f, l0 = 0.f, l1 = 0.f;
    float o[8][4];
    #pragma unroll
    for (int nt = 0; nt < 8; nt++)
        #pragma unroll
        for (int e = 0; e < 4; e++) o[nt][e] = 0.f;

    for (int kb = 0; kb < 2048; kb += 64) {
        __syncthreads();
        // Load K, V tiles (tf32)
        for (int i = tid; i < 1024; i += 128) {
            int r = i >> 4, c = (i & 15) << 2;
            const float* src = qkv + base + (size_t)(kb + r) * 3072;
            float4 kv = *(const float4*)(src + 1024 + c);
            float4 vv = *(const float4*)(src + 2048 + c);
            float4 ko, vo;
            ko.x = __uint_as_float(f2tf32(kv.x));
            ko.y = __uint_as_float(f2tf32(kv.y));
            ko.z = __uint_as_float(f2tf32(kv.z));
            ko.w = __uint_as_float(f2tf32(kv.w));
            vo.x = __uint_as_float(f2tf32(vv.x));
            vo.y = __uint_as_float(f2tf32(vv.y));
            vo.z = __uint_as_float(f2tf32(vv.z));
            vo.w = __uint_as_float(f2tf32(vv.w));
            *(float4*)&Ks[r * FQ + c] = ko;
            *(float4*)&Vs[r * FQ + c] = vo;
        }
        __syncthreads();

        // S = Q @ K^T : m16 (q) x n8 (k-cols) x k8 (d)
        float s[8][4];
        #pragma unroll
        for (int nt = 0; nt < 8; nt++)
            #pragma unroll
            for (int e = 0; e < 4; e++) s[nt][e] = 0.f;

        #pragma unroll
        for (int ks = 0; ks < 8; ks++) {
            uint32_t a[4];
            int rb = (wq + g) * FQ + ks * 8;
            a[0] = __float_as_uint(Qs[rb + t]);
            a[1] = __float_as_uint(Qs[rb + 8 * FQ + t]);
            a[2] = __float_as_uint(Qs[rb + t + 4]);
            a[3] = __float_as_uint(Qs[rb + 8 * FQ + t + 4]);
            #pragma unroll
            for (int nt = 0; nt < 8; nt++) {
                uint32_t bb[2];
                int cb = (nt * 8 + g) * FQ + ks * 8;
                bb[0] = __float_as_uint(Ks[cb + t]);
                bb[1] = __float_as_uint(Ks[cb + t + 4]);
                mma8(s[nt], a, bb);
            }
        }

        // Masks: row0 = qb+wq+g, row1 = +8; cols = kb + nt*8 + t*2 + {0,1}
        {
            int qr0 = qb + wq + g;
            #pragma unroll
            for (int nt = 0; nt < 8; nt++) {
                int col = kb + nt * 8 + t * 2;
                int2 pv = *(const int2*)(pm + b * 2048 + col);
                int2 a0 = *(const int2*)(am + (size_t)qr0 * 2048 + col);
                int2 a1 = *(const int2*)(am + (size_t)(qr0 + 8) * 2048 + col);
                if (a0.x <= 0 || pv.x > 0) s[nt][0] = NEGV;
                if (a0.y <= 0 || pv.y > 0) s[nt][1] = NEGV;
                if (a1.x <= 0 || pv.x > 0) s[nt][2] = NEGV;
                if (a1.y <= 0 || pv.y > 0) s[nt][3] = NEGV;
            }
        }

        // Online softmax. Row is spread over the 4 lanes of a quad -> shfl 1,2.
        float mx0 = -1.0e30f, mx1 = -1.0e30f;
        #pragma unroll
        for (int nt = 0; nt < 8; nt++) {
            mx0 = fmaxf(mx0, fmaxf(s[nt][0], s[nt][1]));
            mx1 = fmaxf(mx1, fmaxf(s[nt][2], s[nt][3]));
        }
        #pragma unroll
        for (int off = 1; off <= 2; off <<= 1) {
            mx0 = fmaxf(mx0, __shfl_xor_sync(0xffffffffu, mx0, off));
            mx1 = fmaxf(mx1, __shfl_xor_sync(0xffffffffu, mx1, off));
        }
        float mn0 = fmaxf(m0, mx0), mn1 = fmaxf(m1, mx1);
        float al0 = fexp(m0 - mn0), al1 = fexp(m1 - mn1);
        m0 = mn0; m1 = mn1;

        float sum0 = 0.f, sum1 = 0.f;
        #pragma unroll
        for (int nt = 0; nt < 8; nt++) {
            s[nt][0] = fexp(s[nt][0] - mn0);
            s[nt][1] = fexp(s[nt][1] - mn0);
            s[nt][2] = fexp(s[nt][2] - mn1);
            s[nt][3] = fexp(s[nt][3] - mn1);
            sum0 += s[nt][0] + s[nt][1];
            sum1 += s[nt][2] + s[nt][3];
        }
        #pragma unroll
        for (int off = 1; off <= 2; off <<= 1) {
            sum0 += __shfl_xor_sync(0xffffffffu, sum0, off);
            sum1 += __shfl_xor_sync(0xffffffffu, sum1, off);
        }
        l0 = l0 * al0 + sum0;
        l1 = l1 * al1 + sum1;
        #pragma unroll
        for (int nt = 0; nt < 8; nt++) {
            o[nt][0] *= al0; o[nt][1] *= al0;
            o[nt][2] *= al1; o[nt][3] *= al1;
        }

        // P -> smem (tf32), rows wq+g and wq+8+g, cols nt*8 + t*2
        #pragma unroll
        for (int nt = 0; nt < 8; nt++) {
            float2 p0 = make_float2(__uint_as_float(f2tf32(s[nt][0])),
                                    __uint_as_float(f2tf32(s[nt][1])));
            float2 p1 = make_float2(__uint_as_float(f2tf32(s[nt][2])),
                                    __uint_as_float(f2tf32(s[nt][3])));
            *(float2*)&Ps[(wq + g) * FQ + nt * 8 + t * 2]     = p0;
            *(float2*)&Ps[(wq + 8 + g) * FQ + nt * 8 + t * 2] = p1;
        }
        __syncwarp();

        // O += P @ V : m16 (q) x n8 (d-cols) x k8 (k)
        #pragma unroll
        for (int ks = 0; ks < 8; ks++) {
            uint32_t a[4];
            int rb = (wq + g) * FQ + ks * 8;
            a[0] = __float_as_uint(Ps[rb + t]);
            a[1] = __float_as_uint(Ps[rb + 8 * FQ + t]);
            a[2] = __float_as_uint(Ps[rb + t + 4]);
            a[3] = __float_as_uint(Ps[rb + 8 * FQ + t + 4]);
            #pragma unroll
            for (int nt = 0; nt < 8; nt++) {
                uint32_t bb[2];
                int vb0 = (ks * 8 + t) * FQ + nt * 8 + g;
                bb[0] = __float_as_uint(Vs[vb0]);
                bb[1] = __float_as_uint(Vs[vb0 + 4 * FQ]);
                mma8(o[nt], a, bb);
            }
        }
        __syncwarp();
    }

    // Epilogue: normalize, write [B*N, C], col = h*64 + d
    float inv0 = 1.0f / l0, inv1 = 1.0f / l1;
    int row0 = b * 2048 + qb + wq + g;
    #pragma unroll
    for (int nt = 0; nt < 8; nt++) {
        int col = h * 64 + nt * 8 + t * 2;
        float2 v0 = make_float2(o[nt][0] * inv0, o[nt][1] * inv0);
        float2 v1 = make_float2(o[nt][2] * inv1, o[nt][3] * inv1);
        *(float2*)&out[(size_t)row0 * 1024 + col]       = v0;
        *(float2*)&out[(size_t)(row0 + 8) * 1024 + col] = v1;
    }
}

// ---------------------------------------------------------------------------
extern "C" void kernel_launch(void* const* d_in, const int* in_sizes, int n_in,
                              void* d_out, int out_size) {
    const float* inputs = (const float*)d_in[0];
    const int*   amask  = (const int*)d_in[1];
    const int*   pmask  = (const int*)d_in[2];
    const float* Wqkv   = (const float*)d_in[3];
    const float* Wproj  = (const float*)d_in[4];
    const float* bproj  = (const float*)d_in[5];
    float* out = (float*)d_out;

    float *qkv_p, *att_p;
    cudaGetSymbolAddress((void**)&qkv_p, g_qkv);
    cudaGetSymbolAddress((void**)&att_p, g_att);

    // 1) QKV = X @ W_qkv : [8192,1024] x [1024,3072]  (tf32x3)
    gemm_tf32x3<<<dim3(24, 64), 256>>>(inputs, Wqkv, nullptr, qkv_p,
                                       8192, 3072, 1024);

    // 2) Flash attention (tf32 mma)
    cudaFuncSetAttribute(flash_mma, cudaFuncAttributeMaxDynamicSharedMemorySize,
                         FLASH_SMEM);
    flash_mma<<<dim3(32, 16, 4), 128, FLASH_SMEM>>>(qkv_p, amask, pmask, att_p);

    // 3) Out = Att @ W_proj + b : [8192,1024] x [1024,1024]  (tf32x3)
    gemm_tf32x3<<<dim3(8, 64), 256>>>(att_p, Wproj, bproj, out,
                                      8192, 1024, 1024);
}